// round 7
// baseline (speedup 1.0000x reference)
#include <cuda_runtime.h>
#include <cuda_bf16.h>
#include <mma.h>
#include <math.h>
#include <stdint.h>

using namespace nvcuda;

// ---------------- problem constants ----------------
#define B_     32
#define S_     197
#define BS_    (B_ * S_)      // 6304
#define D_     768
#define F_     3072
#define H_     12
#define DH_    64
#define L_     12
#define NPATCH 196            // 14*14
#define NCLS_  1000

// ---------------- scratch (device globals; no allocation allowed) ----------------
__device__ float g_x   [BS_ * D_];
__device__ float g_lnb [BS_ * D_];
__device__ float g_q   [BS_ * D_];
__device__ float g_k   [BS_ * D_];
__device__ float g_v   [BS_ * D_];
__device__ float g_attn[BS_ * D_];
__device__ float g_ffh [(size_t)BS_ * F_];
__device__ float g_sc  [(size_t)B_ * H_ * S_ * S_];
__device__ float g_im  [B_ * NPATCH * D_];
__device__ float g_pe  [B_ * NPATCH * D_];
__device__ float g_wpt [D_ * D_];

// ---------------- im2col for 16x16 stride-16 patches ----------------
__global__ void im2col_kernel(const float* __restrict__ X, float* __restrict__ out) {
    int idx = blockIdx.x * blockDim.x + threadIdx.x;
    if (idx >= B_ * NPATCH * D_) return;
    int col = idx % D_;
    int row = idx / D_;
    int b  = row / NPATCH;
    int pp = row % NPATCH;
    int ph = pp / 14, pw = pp % 14;
    int c = col >> 8;
    int p = (col >> 4) & 15;
    int q = col & 15;
    out[idx] = X[((size_t)(b * 3 + c) * 224 + (ph * 16 + p)) * 224 + (pw * 16 + q)];
}

__global__ void transpose768_kernel(const float* __restrict__ W, float* __restrict__ Wt) {
    int idx = blockIdx.x * blockDim.x + threadIdx.x;
    if (idx >= D_ * D_) return;
    int d = idx / D_;
    int k = idx % D_;
    Wt[k * D_ + d] = W[d * D_ + k];
}

__global__ void assemble_kernel(const float* __restrict__ pe, const float* __restrict__ cls,
                                const float* __restrict__ pos, float* __restrict__ x) {
    int idx = blockIdx.x * blockDim.x + threadIdx.x;
    if (idx >= BS_ * D_) return;
    int d  = idx % D_;
    int bs = idx / D_;
    int s = bs % S_;
    int b = bs / S_;
    float v = (s == 0) ? cls[d] : pe[((size_t)b * NPATCH + (s - 1)) * D_ + d];
    x[idx] = v + pos[s * D_ + d];
}

// ---------------- bf16 split helper: v = hi + lo (each bf16) ----------------
__device__ __forceinline__ void split_pair(float x, float y,
                                           __nv_bfloat162& h, __nv_bfloat162& l) {
    __nv_bfloat16 hx = __float2bfloat16(x);
    __nv_bfloat16 hy = __float2bfloat16(y);
    float lx = x - __bfloat162float(hx);
    float ly = y - __bfloat162float(hy);
    h = __halves2bfloat162(hx, hy);
    l = __halves2bfloat162(__float2bfloat16(lx), __float2bfloat16(ly));
}

// ---------------- tensor-core GEMM (bf16 hi/lo split, 3 MMAs -> ~fp32 accuracy) ----
// C[MxN] = A[MxK] @ B[KxN] + bias, epi: 0 none, 1 +residual R, 2 GELU(exact)
// BM=128 BN=128 BK=32, 256 threads (8 warps, each 64x32)
#define LDA_ 40
#define LDB_ 136
#define LDS_T 20

__global__ __launch_bounds__(256, 1)
void gemm_bf16x3_kernel(const float* __restrict__ A, const float* __restrict__ Bw,
                        const float* __restrict__ bias, const float* __restrict__ R,
                        float* __restrict__ C, int M, int N, int K, int epi)
{
    __shared__ __align__(32) __nv_bfloat16 As_h[128 * LDA_];
    __shared__ __align__(32) __nv_bfloat16 As_l[128 * LDA_];
    __shared__ __align__(32) __nv_bfloat16 Bs_h[32 * LDB_];
    __shared__ __align__(32) __nv_bfloat16 Bs_l[32 * LDB_];
    __shared__ __align__(32) float stage[8 * 16 * LDS_T];

    const int tid  = threadIdx.x;
    const int wid  = tid >> 5;
    const int lane = tid & 31;
    const int warpRow = wid >> 2;     // 0..1  (64 rows each)
    const int warpCol = wid & 3;      // 0..3  (32 cols each)
    const int brow = blockIdx.y * 128;
    const int bcol = blockIdx.x * 128;

    // A loader: 2 threads per row, 16 floats each
    const int ar = tid >> 1;
    const int ac = (tid & 1) * 16;
    const bool aValid = (brow + ar) < M;
    const float* Aptr = A + (size_t)(brow + ar) * K + ac;
    // B loader: 8 threads per row (32 rows), 16 floats each
    const int br = tid >> 3;
    const int bc = (tid & 7) * 16;
    const float* Bptr = Bw + (size_t)br * N + bcol + bc;

    wmma::fragment<wmma::accumulator, 16, 16, 16, float> acc[4][2];
#pragma unroll
    for (int i = 0; i < 4; i++)
#pragma unroll
        for (int j = 0; j < 2; j++) wmma::fill_fragment(acc[i][j], 0.0f);

    for (int k0 = 0; k0 < K; k0 += 32) {
        // ---- load + split A tile [128 x 32] ----
        {
            __nv_bfloat162* dh = reinterpret_cast<__nv_bfloat162*>(&As_h[ar * LDA_ + ac]);
            __nv_bfloat162* dl = reinterpret_cast<__nv_bfloat162*>(&As_l[ar * LDA_ + ac]);
#pragma unroll
            for (int u = 0; u < 4; u++) {
                float4 v = make_float4(0.f, 0.f, 0.f, 0.f);
                if (aValid) v = *reinterpret_cast<const float4*>(Aptr + k0 + u * 4);
                __nv_bfloat162 h0, l0, h1, l1;
                split_pair(v.x, v.y, h0, l0);
                split_pair(v.z, v.w, h1, l1);
                dh[u * 2 + 0] = h0; dh[u * 2 + 1] = h1;
                dl[u * 2 + 0] = l0; dl[u * 2 + 1] = l1;
            }
        }
        // ---- load + split B tile [32 x 128] ----
        {
            __nv_bfloat162* dh = reinterpret_cast<__nv_bfloat162*>(&Bs_h[br * LDB_ + bc]);
            __nv_bfloat162* dl = reinterpret_cast<__nv_bfloat162*>(&Bs_l[br * LDB_ + bc]);
#pragma unroll
            for (int u = 0; u < 4; u++) {
                float4 v = *reinterpret_cast<const float4*>(Bptr + (size_t)k0 * N + u * 4);
                __nv_bfloat162 h0, l0, h1, l1;
                split_pair(v.x, v.y, h0, l0);
                split_pair(v.z, v.w, h1, l1);
                dh[u * 2 + 0] = h0; dh[u * 2 + 1] = h1;
                dl[u * 2 + 0] = l0; dl[u * 2 + 1] = l1;
            }
        }
        __syncthreads();

#pragma unroll
        for (int kk = 0; kk < 32; kk += 16) {
            wmma::fragment<wmma::matrix_b, 16, 16, 16, __nv_bfloat16, wmma::row_major> fb_h[2], fb_l[2];
#pragma unroll
            for (int j = 0; j < 2; j++) {
                int cb = warpCol * 32 + j * 16;
                wmma::load_matrix_sync(fb_h[j], &Bs_h[kk * LDB_ + cb], LDB_);
                wmma::load_matrix_sync(fb_l[j], &Bs_l[kk * LDB_ + cb], LDB_);
            }
#pragma unroll
            for (int i = 0; i < 4; i++) {
                wmma::fragment<wmma::matrix_a, 16, 16, 16, __nv_bfloat16, wmma::row_major> fa_h, fa_l;
                int rb = warpRow * 64 + i * 16;
                wmma::load_matrix_sync(fa_h, &As_h[rb * LDA_ + kk], LDA_);
                wmma::load_matrix_sync(fa_l, &As_l[rb * LDA_ + kk], LDA_);
#pragma unroll
                for (int j = 0; j < 2; j++) {
                    wmma::mma_sync(acc[i][j], fa_h, fb_h[j], acc[i][j]);
                    wmma::mma_sync(acc[i][j], fa_h, fb_l[j], acc[i][j]);
                    wmma::mma_sync(acc[i][j], fa_l, fb_h[j], acc[i][j]);
                }
            }
        }
        __syncthreads();
    }

    // ---- epilogue: per-warp smem staging, fused bias / residual / GELU ----
    float* st = stage + wid * 16 * LDS_T;
#pragma unroll
    for (int i = 0; i < 4; i++) {
#pragma unroll
        for (int j = 0; j < 2; j++) {
            wmma::store_matrix_sync(st, acc[i][j], LDS_T, wmma::mem_row_major);
            __syncwarp();
            int gr0 = brow + warpRow * 64 + i * 16;
            int gc0 = bcol + warpCol * 32 + j * 16;
#pragma unroll
            for (int e = 0; e < 8; e++) {
                int idx = e * 32 + lane;
                int r = idx >> 4, c = idx & 15;
                int gr = gr0 + r;
                if (gr < M) {
                    float v = st[r * LDS_T + c] + bias[gc0 + c];
                    if (epi == 1) {
                        v += R[(size_t)gr * N + gc0 + c];
                    } else if (epi == 2) {
                        v = 0.5f * v * (1.0f + erff(v * 0.70710678118654752f));
                    }
                    C[(size_t)gr * N + gc0 + c] = v;
                }
            }
            __syncwarp();
        }
    }
}

// ---------------- LayerNorm (row of 768), two-pass via smem cache ----------------
__global__ void layernorm_kernel(const float* __restrict__ x, const float* __restrict__ g,
                                 const float* __restrict__ b, float* __restrict__ out)
{
    __shared__ float xs[D_];
    __shared__ float red[8];
    __shared__ float s_mean, s_rstd;

    int row = blockIdx.x;
    const float* xr = x + (size_t)row * D_;
    int tid  = threadIdx.x;
    int lane = tid & 31, warp = tid >> 5;

    float s = 0.f;
    for (int i = tid; i < D_; i += 256) { float v = xr[i]; xs[i] = v; s += v; }
#pragma unroll
    for (int o = 16; o; o >>= 1) s += __shfl_xor_sync(0xffffffffu, s, o);
    if (lane == 0) red[warp] = s;
    __syncthreads();
    if (tid == 0) {
        float t = 0.f;
#pragma unroll
        for (int w = 0; w < 8; w++) t += red[w];
        s_mean = t * (1.0f / D_);
    }
    __syncthreads();
    float m = s_mean;

    float v2 = 0.f;
    for (int i = tid; i < D_; i += 256) { float dv = xs[i] - m; v2 += dv * dv; }
#pragma unroll
    for (int o = 16; o; o >>= 1) v2 += __shfl_xor_sync(0xffffffffu, v2, o);
    if (lane == 0) red[warp] = v2;
    __syncthreads();
    if (tid == 0) {
        float t = 0.f;
#pragma unroll
        for (int w = 0; w < 8; w++) t += red[w];
        s_rstd = rsqrtf(t * (1.0f / D_) + 1e-5f);
    }
    __syncthreads();
    float rstd = s_rstd;

    float* orow = out + (size_t)row * D_;
    for (int i = tid; i < D_; i += 256)
        orow[i] = (xs[i] - m) * rstd * g[i] + b[i];
}

// ---------------- attention: scores = scale * Q Kt (per b,h; 64x64 tiles) ----------------
__global__ __launch_bounds__(256)
void qk_kernel(const float* __restrict__ Q, const float* __restrict__ Kk, float* __restrict__ Sc)
{
    const int PITCH = 68;
    __shared__ __align__(16) float Qs[64 * PITCH];
    __shared__ __align__(16) float Ks[64 * PITCH];

    int bh = blockIdx.z;
    int b = bh / H_, h = bh % H_;
    int s0 = blockIdx.y * 64, t0 = blockIdx.x * 64;
    const float* Qb = Q + (size_t)b * S_ * D_ + h * DH_;
    const float* Kb = Kk + (size_t)b * S_ * D_ + h * DH_;
    int tid = threadIdx.x;

#pragma unroll
    for (int k = 0; k < 16; k++) {
        int idx = tid + k * 256;
        int r = idx >> 6, d = idx & 63;
        float qv = 0.f, kv = 0.f;
        if (s0 + r < S_) qv = Qb[(size_t)(s0 + r) * D_ + d];
        if (t0 + r < S_) kv = Kb[(size_t)(t0 + r) * D_ + d];
        Qs[d * PITCH + r] = qv;
        Ks[d * PITCH + r] = kv;
    }
    __syncthreads();

    int tx = tid & 15, ty = tid >> 4;
    float acc[4][4];
#pragma unroll
    for (int i = 0; i < 4; i++)
#pragma unroll
        for (int j = 0; j < 4; j++) acc[i][j] = 0.f;

#pragma unroll 4
    for (int d = 0; d < 64; d++) {
        float4 a = *reinterpret_cast<const float4*>(&Qs[d * PITCH + ty * 4]);
        float4 bb = *reinterpret_cast<const float4*>(&Ks[d * PITCH + tx * 4]);
        float ar[4] = {a.x, a.y, a.z, a.w};
        float br[4] = {bb.x, bb.y, bb.z, bb.w};
#pragma unroll
        for (int i = 0; i < 4; i++)
#pragma unroll
            for (int j = 0; j < 4; j++) acc[i][j] += ar[i] * br[j];
    }

    float* Sb = Sc + (size_t)bh * S_ * S_;
#pragma unroll
    for (int i = 0; i < 4; i++) {
        int s = s0 + ty * 4 + i;
        if (s >= S_) continue;
#pragma unroll
        for (int j = 0; j < 4; j++) {
            int t = t0 + tx * 4 + j;
            if (t >= S_) continue;
            Sb[(size_t)s * S_ + t] = acc[i][j] * 0.125f;
        }
    }
}

// ---------------- softmax over last dim (rows of 197), one warp per row ----------------
__global__ void softmax_kernel(float* __restrict__ p, int nrows)
{
    int row = blockIdx.x * 8 + (threadIdx.x >> 5);
    if (row >= nrows) return;
    int lane = threadIdx.x & 31;
    float* pr = p + (size_t)row * S_;

    float m = -1e30f;
    for (int t = lane; t < S_; t += 32) m = fmaxf(m, pr[t]);
#pragma unroll
    for (int o = 16; o; o >>= 1) m = fmaxf(m, __shfl_xor_sync(0xffffffffu, m, o));

    float s = 0.f;
    for (int t = lane; t < S_; t += 32) { float e = expf(pr[t] - m); pr[t] = e; s += e; }
#pragma unroll
    for (int o = 16; o; o >>= 1) s += __shfl_xor_sync(0xffffffffu, s, o);

    float inv = 1.0f / s;
    for (int t = lane; t < S_; t += 32) pr[t] *= inv;
}

// ---------------- attention: O = P @ V ----------------
__global__ __launch_bounds__(256)
void pv_kernel(const float* __restrict__ P, const float* __restrict__ V, float* __restrict__ O)
{
    const int PITCH = 68;
    __shared__ __align__(16) float Ps[32 * PITCH];
    __shared__ __align__(16) float Vs[32 * PITCH];

    int bh = blockIdx.y;
    int b = bh / H_, h = bh % H_;
    int s0 = blockIdx.x * 64;
    const float* Pb = P + (size_t)bh * S_ * S_;
    const float* Vb = V + (size_t)b * S_ * D_ + h * DH_;
    int tid = threadIdx.x;
    int tx = tid & 15, ty = tid >> 4;

    float acc[4][4];
#pragma unroll
    for (int i = 0; i < 4; i++)
#pragma unroll
        for (int j = 0; j < 4; j++) acc[i][j] = 0.f;

    for (int t0 = 0; t0 < S_; t0 += 32) {
#pragma unroll
        for (int k = 0; k < 8; k++) {
            int idx = tid + k * 256;
            int r = idx >> 5, t = idx & 31;
            float pv = 0.f;
            if (s0 + r < S_ && t0 + t < S_) pv = Pb[(size_t)(s0 + r) * S_ + t0 + t];
            Ps[t * PITCH + r] = pv;
        }
#pragma unroll
        for (int k = 0; k < 8; k++) {
            int idx = tid + k * 256;
            int t = idx >> 6, d = idx & 63;
            float vv = 0.f;
            if (t0 + t < S_) vv = Vb[(size_t)(t0 + t) * D_ + d];
            Vs[t * PITCH + d] = vv;
        }
        __syncthreads();

#pragma unroll 4
        for (int t = 0; t < 32; t++) {
            float4 a = *reinterpret_cast<const float4*>(&Ps[t * PITCH + ty * 4]);
            float4 bb = *reinterpret_cast<const float4*>(&Vs[t * PITCH + tx * 4]);
            float ar[4] = {a.x, a.y, a.z, a.w};
            float br[4] = {bb.x, bb.y, bb.z, bb.w};
#pragma unroll
            for (int i = 0; i < 4; i++)
#pragma unroll
                for (int j = 0; j < 4; j++) acc[i][j] += ar[i] * br[j];
        }
        __syncthreads();
    }

#pragma unroll
    for (int i = 0; i < 4; i++) {
        int s = s0 + ty * 4 + i;
        if (s >= S_) continue;
#pragma unroll
        for (int j = 0; j < 4; j++) {
            int d = tx * 4 + j;
            O[((size_t)(b * S_ + s)) * D_ + h * DH_ + d] = acc[i][j];
        }
    }
}

// ---------------- classification head ----------------
__global__ void head_kernel(const float* __restrict__ Xn, const float* __restrict__ W,
                            const float* __restrict__ bias, float* __restrict__ out)
{
    __shared__ float xs[D_];
    int b = blockIdx.y;
    const float* xr = Xn + (size_t)b * S_ * D_;
    for (int i = threadIdx.x; i < D_; i += 256) xs[i] = xr[i];
    __syncthreads();

    int n = blockIdx.x * 256 + threadIdx.x;
    if (n >= NCLS_) return;
    float s = bias[n];
    for (int k = 0; k < D_; k++) s += xs[k] * W[(size_t)k * NCLS_ + n];
    out[b * NCLS_ + n] = s;
}

// ---------------- host launch ----------------
static inline void run_gemm(const float* A, const float* Bw, const float* bias,
                            const float* R, float* C, int M, int N, int K, int epi)
{
    dim3 grid(N / 128, (M + 127) / 128);
    gemm_bf16x3_kernel<<<grid, 256>>>(A, Bw, bias, R, C, M, N, K, epi);
}

extern "C" void kernel_launch(void* const* d_in, const int* in_sizes, int n_in,
                              void* d_out, int out_size)
{
    const float* X       = (const float*)d_in[0];
    const float* patch_w = (const float*)d_in[1];
    const float* patch_b = (const float*)d_in[2];
    const float* cls_tok = (const float*)d_in[3];
    const float* pos_emb = (const float*)d_in[4];
    const float* ln1_g   = (const float*)d_in[5];
    const float* ln1_b   = (const float*)d_in[6];
    const float* Wq      = (const float*)d_in[7];
    const float* bq      = (const float*)d_in[8];
    const float* Wk      = (const float*)d_in[9];
    const float* bk      = (const float*)d_in[10];
    const float* Wv      = (const float*)d_in[11];
    const float* bv      = (const float*)d_in[12];
    const float* Wo      = (const float*)d_in[13];
    const float* bo      = (const float*)d_in[14];
    const float* ln2_g   = (const float*)d_in[15];
    const float* ln2_b   = (const float*)d_in[16];
    const float* Wf1     = (const float*)d_in[17];
    const float* bf1     = (const float*)d_in[18];
    const float* Wf2     = (const float*)d_in[19];
    const float* bf2     = (const float*)d_in[20];
    const float* lnf_g   = (const float*)d_in[21];
    const float* lnf_b   = (const float*)d_in[22];
    const float* head_w  = (const float*)d_in[23];
    const float* head_b  = (const float*)d_in[24];
    float* out = (float*)d_out;
    (void)in_sizes; (void)n_in; (void)out_size;

    float *px, *pln, *pq, *pk, *pv, *pattn, *pffh, *psc, *pim, *ppe, *pwpt;
    cudaGetSymbolAddress((void**)&px,   g_x);
    cudaGetSymbolAddress((void**)&pln,  g_lnb);
    cudaGetSymbolAddress((void**)&pq,   g_q);
    cudaGetSymbolAddress((void**)&pk,   g_k);
    cudaGetSymbolAddress((void**)&pv,   g_v);
    cudaGetSymbolAddress((void**)&pattn,g_attn);
    cudaGetSymbolAddress((void**)&pffh, g_ffh);
    cudaGetSymbolAddress((void**)&psc,  g_sc);
    cudaGetSymbolAddress((void**)&pim,  g_im);
    cudaGetSymbolAddress((void**)&ppe,  g_pe);
    cudaGetSymbolAddress((void**)&pwpt, g_wpt);

    // --- patch embedding ---
    {
        int n1 = B_ * NPATCH * D_;
        im2col_kernel<<<(n1 + 255) / 256, 256>>>(X, pim);
        transpose768_kernel<<<(D_ * D_ + 255) / 256, 256>>>(patch_w, pwpt);
        run_gemm(pim, pwpt, patch_b, nullptr, ppe, B_ * NPATCH, D_, D_, 0);
        int n2 = BS_ * D_;
        assemble_kernel<<<(n2 + 255) / 256, 256>>>(ppe, cls_tok, pos_emb, px);
    }

    const int nrows_sm = B_ * H_ * S_;

    for (int l = 0; l < L_; l++) {
        const float* wq = Wq + (size_t)l * D_ * D_;
        const float* wk = Wk + (size_t)l * D_ * D_;
        const float* wv = Wv + (size_t)l * D_ * D_;
        const float* wo = Wo + (size_t)l * D_ * D_;
        const float* w1 = Wf1 + (size_t)l * D_ * F_;
        const float* w2 = Wf2 + (size_t)l * F_ * D_;

        layernorm_kernel<<<BS_, 256>>>(px, ln1_g + l * D_, ln1_b + l * D_, pln);

        run_gemm(pln, wq, bq + l * D_, nullptr, pq, BS_, D_, D_, 0);
        run_gemm(pln, wk, bk + l * D_, nullptr, pk, BS_, D_, D_, 0);
        run_gemm(pln, wv, bv + l * D_, nullptr, pv, BS_, D_, D_, 0);

        {
            dim3 grid((S_ + 63) / 64, (S_ + 63) / 64, B_ * H_);
            qk_kernel<<<grid, 256>>>(pq, pk, psc);
        }
        softmax_kernel<<<(nrows_sm + 7) / 8, 256>>>(psc, nrows_sm);
        {
            dim3 grid((S_ + 63) / 64, B_ * H_);
            pv_kernel<<<grid, 256>>>(psc, pv, pattn);
        }

        run_gemm(pattn, wo, bo + l * D_, px, px, BS_, D_, D_, 1);

        layernorm_kernel<<<BS_, 256>>>(px, ln2_g + l * D_, ln2_b + l * D_, pln);
        run_gemm(pln, w1, bf1 + l * F_, nullptr, pffh, BS_, F_, D_, 2);
        run_gemm(pffh, w2, bf2 + l * D_, px, px, BS_, D_, F_, 1);
    }

    layernorm_kernel<<<BS_, 256>>>(px, lnf_g, lnf_b, pln);
    {
        dim3 grid((NCLS_ + 255) / 256, B_);
        head_kernel<<<grid, 256>>>(pln, head_w, head_b, out);
    }
}

// round 8
// speedup vs baseline: 1.4377x; 1.4377x over previous
#include <cuda_runtime.h>
#include <cuda_bf16.h>
#include <mma.h>
#include <math.h>
#include <stdint.h>

using namespace nvcuda;

// ---------------- problem constants ----------------
#define B_     32
#define S_     197
#define BS_    (B_ * S_)      // 6304
#define D_     768
#define F_     3072
#define H_     12
#define DH_    64
#define L_     12
#define NPATCH 196
#define NCLS_  1000
#define QS_    2304           // fused qkv row stride

typedef __nv_bfloat16 bf16;

// ---------------- scratch (device globals; no allocation allowed) ----------------
__device__ float g_x   [BS_ * D_];
__device__ float g_lnb [BS_ * D_];
__device__ bf16  g_lnh [BS_ * D_];
__device__ bf16  g_lnl [BS_ * D_];
__device__ float g_qkv [(size_t)BS_ * QS_];
__device__ bf16  g_attnh[BS_ * D_];
__device__ bf16  g_attnl[BS_ * D_];
__device__ bf16  g_ffhh[(size_t)BS_ * F_];
__device__ bf16  g_ffhl[(size_t)BS_ * F_];
__device__ float g_sc  [(size_t)B_ * H_ * S_ * S_];
__device__ bf16  g_imh [B_ * NPATCH * D_];
__device__ bf16  g_iml [B_ * NPATCH * D_];
__device__ float g_pe  [B_ * NPATCH * D_];
// pre-split weights (bf16 hi/lo)
__device__ bf16  g_wpt_h[D_ * D_];
__device__ bf16  g_wpt_l[D_ * D_];
__device__ bf16  g_wqkv_h[(size_t)L_ * D_ * QS_];
__device__ bf16  g_wqkv_l[(size_t)L_ * D_ * QS_];
__device__ float g_bqkv [L_ * QS_];
__device__ bf16  g_wo_h[(size_t)L_ * D_ * D_];
__device__ bf16  g_wo_l[(size_t)L_ * D_ * D_];
__device__ bf16  g_wf1_h[(size_t)L_ * D_ * F_];
__device__ bf16  g_wf1_l[(size_t)L_ * D_ * F_];
__device__ bf16  g_wf2_h[(size_t)L_ * F_ * D_];
__device__ bf16  g_wf2_l[(size_t)L_ * F_ * D_];

// ---------------- helpers ----------------
__device__ __forceinline__ void splitv(float v, bf16& h, bf16& l) {
    h = __float2bfloat16(v);
    l = __float2bfloat16(v - __bfloat162float(h));
}
__device__ __forceinline__ uint32_t smem_u32(const void* p) {
    return (uint32_t)__cvta_generic_to_shared(p);
}
__device__ __forceinline__ void cp16(uint32_t dst, const void* src, bool pred) {
    int sz = pred ? 16 : 0;
    asm volatile("cp.async.cg.shared.global [%0], [%1], 16, %2;\n"
                 :: "r"(dst), "l"(src), "r"(sz));
}

// ---------------- prep: weight splitting ----------------
__global__ void split_kernel(const float* __restrict__ src, bf16* __restrict__ h,
                             bf16* __restrict__ l, size_t n) {
    size_t i = (size_t)blockIdx.x * 256 + threadIdx.x;
    if (i >= n) return;
    splitv(src[i], h[i], l[i]);
}

__global__ void qkv_split_kernel(const float* __restrict__ Wq, const float* __restrict__ Wk,
                                 const float* __restrict__ Wv,
                                 bf16* __restrict__ h, bf16* __restrict__ l) {
    size_t i = (size_t)blockIdx.x * 256 + threadIdx.x;
    if (i >= (size_t)L_ * D_ * QS_) return;
    int n = (int)(i % QS_);
    size_t rest = i / QS_;
    int k = (int)(rest % D_);
    int lay = (int)(rest / D_);
    const float* src = (n < 768) ? Wq : (n < 1536) ? Wk : Wv;
    float v = src[((size_t)lay * D_ + k) * D_ + (n % 768)];
    splitv(v, h[i], l[i]);
}

__global__ void qkv_bias_kernel(const float* __restrict__ bq, const float* __restrict__ bk,
                                const float* __restrict__ bv, float* __restrict__ out) {
    int i = blockIdx.x * 256 + threadIdx.x;
    if (i >= L_ * QS_) return;
    int n = i % QS_, lay = i / QS_;
    const float* src = (n < 768) ? bq : (n < 1536) ? bk : bv;
    out[i] = src[lay * D_ + (n % 768)];
}

__global__ void transpose_split_kernel(const float* __restrict__ W,
                                       bf16* __restrict__ h, bf16* __restrict__ l) {
    int idx = blockIdx.x * 256 + threadIdx.x;
    if (idx >= D_ * D_) return;
    int d = idx / D_, k = idx % D_;
    splitv(W[idx], h[k * D_ + d], l[k * D_ + d]);
}

// ---------------- im2col (writes bf16 hi/lo) ----------------
__global__ void im2col_kernel(const float* __restrict__ X,
                              bf16* __restrict__ oh, bf16* __restrict__ ol) {
    int idx = blockIdx.x * blockDim.x + threadIdx.x;
    if (idx >= B_ * NPATCH * D_) return;
    int col = idx % D_;
    int row = idx / D_;
    int b  = row / NPATCH;
    int pp = row % NPATCH;
    int ph = pp / 14, pw = pp % 14;
    int c = col >> 8;
    int p = (col >> 4) & 15;
    int q = col & 15;
    float v = X[((size_t)(b * 3 + c) * 224 + (ph * 16 + p)) * 224 + (pw * 16 + q)];
    splitv(v, oh[idx], ol[idx]);
}

__global__ void assemble_kernel(const float* __restrict__ pe, const float* __restrict__ cls,
                                const float* __restrict__ pos, float* __restrict__ x) {
    int idx = blockIdx.x * blockDim.x + threadIdx.x;
    if (idx >= BS_ * D_) return;
    int d  = idx % D_;
    int bs = idx / D_;
    int s = bs % S_;
    int b = bs / S_;
    float v = (s == 0) ? cls[d] : pe[((size_t)b * NPATCH + (s - 1)) * D_ + d];
    x[idx] = v + pos[s * D_ + d];
}

// ---------------- dual-bf16 tensor-core GEMM with cp.async double buffering ----
// C[MxN] = (Ah+Al)[MxK] @ (Bh+Bl)[KxN] + bias   (3-term MMA, ~fp32 accuracy)
// epi: 0 -> Cf = v ; 1 -> Cf = v + R ; 2 -> (Ch,Cl) = split(GELU(v))
// BM=128 BN=256 BK=32, 512 threads (16 warps, 4x4, warp tile 32x64)
#define PA 40    // A smem pitch (bf16)
#define PB 264   // B smem pitch (bf16)
#define GEMM_SMEM 129024

__global__ __launch_bounds__(512, 1)
void gemm_dual_kernel(const bf16* __restrict__ Agh, const bf16* __restrict__ Agl,
                      const bf16* __restrict__ Bgh, const bf16* __restrict__ Bgl,
                      const float* __restrict__ bias, const float* __restrict__ R,
                      float* __restrict__ Cf, bf16* __restrict__ Ch, bf16* __restrict__ Cl,
                      int M, int N, int K, int epi)
{
    extern __shared__ char dsm[];
    bf16* sAh = (bf16*)dsm;                          // 2 * 128*PA
    bf16* sAl = sAh + 2 * 128 * PA;
    bf16* sBh = sAl + 2 * 128 * PA;                  // 2 * 32*PB
    bf16* sBl = sBh + 2 * 32 * PB;
    float* sStage = (float*)(sBl + 2 * 32 * PB);     // 16 * 16*20

    const int tid  = threadIdx.x;
    const int wid  = tid >> 5;
    const int lane = tid & 31;
    const int warpRow = wid >> 2;     // 0..3 (32 rows)
    const int warpCol = wid & 3;      // 0..3 (64 cols)
    const int brow = blockIdx.y * 128;
    const int bcol = blockIdx.x * 256;

    // A loader: 512 chunks of 16B (128 rows x 4)
    const int arow = tid >> 2;
    const int ac8  = (tid & 3) * 8;
    const bool aOk = (brow + arow) < M;
    const int aRowG = aOk ? (brow + arow) : (M - 1);
    const bf16* aSrcH = Agh + (size_t)aRowG * K + ac8;
    const bf16* aSrcL = Agl + (size_t)aRowG * K + ac8;
    const uint32_t aDstH0 = smem_u32(sAh + arow * PA + ac8);
    const uint32_t aDstL0 = smem_u32(sAl + arow * PA + ac8);
    // B loader: 1024 chunks (32 rows x 32), 2 per thread
    const int brow0 = tid >> 5,          bcc0 = (tid & 31) * 8;
    const int brow1 = (tid + 512) >> 5,  bcc1 = bcc0;
    const uint32_t bDstH0 = smem_u32(sBh + brow0 * PB + bcc0);
    const uint32_t bDstH1 = smem_u32(sBh + brow1 * PB + bcc1);
    const uint32_t bDstL0 = smem_u32(sBl + brow0 * PB + bcc0);
    const uint32_t bDstL1 = smem_u32(sBl + brow1 * PB + bcc1);

    const int bufA = 128 * PA * 2;   // bytes per A buffer
    const int bufB = 32 * PB * 2;    // bytes per B buffer

    auto issue = [&](int k0, int buf) {
        cp16(aDstH0 + buf * bufA, aSrcH + k0, aOk);
        cp16(aDstL0 + buf * bufA, aSrcL + k0, aOk);
        const bf16* bh = Bgh + (size_t)k0 * N + bcol;
        const bf16* bl = Bgl + (size_t)k0 * N + bcol;
        cp16(bDstH0 + buf * bufB, bh + (size_t)brow0 * N + bcc0, true);
        cp16(bDstH1 + buf * bufB, bh + (size_t)brow1 * N + bcc1, true);
        cp16(bDstL0 + buf * bufB, bl + (size_t)brow0 * N + bcc0, true);
        cp16(bDstL1 + buf * bufB, bl + (size_t)brow1 * N + bcc1, true);
    };

    wmma::fragment<wmma::accumulator, 16, 16, 16, float> acc[2][4];
#pragma unroll
    for (int i = 0; i < 2; i++)
#pragma unroll
        for (int j = 0; j < 4; j++) wmma::fill_fragment(acc[i][j], 0.0f);

    const int T = K / 32;
    issue(0, 0);
    asm volatile("cp.async.commit_group;\n");

    for (int it = 0; it < T; ++it) {
        if (it + 1 < T) {
            issue((it + 1) * 32, (it + 1) & 1);
            asm volatile("cp.async.commit_group;\n");
            asm volatile("cp.async.wait_group 1;\n");
        } else {
            asm volatile("cp.async.wait_group 0;\n");
        }
        __syncthreads();

        const int buf = it & 1;
        const bf16* cAh = sAh + buf * 128 * PA;
        const bf16* cAl = sAl + buf * 128 * PA;
        const bf16* cBh = sBh + buf * 32 * PB;
        const bf16* cBl = sBl + buf * 32 * PB;

#pragma unroll
        for (int kk = 0; kk < 32; kk += 16) {
            wmma::fragment<wmma::matrix_b, 16, 16, 16, bf16, wmma::row_major> fbh[4], fbl[4];
#pragma unroll
            for (int j = 0; j < 4; j++) {
                const bf16* pb = cBh + kk * PB + warpCol * 64 + j * 16;
                wmma::load_matrix_sync(fbh[j], pb, PB);
                wmma::load_matrix_sync(fbl[j], cBl + kk * PB + warpCol * 64 + j * 16, PB);
            }
#pragma unroll
            for (int i = 0; i < 2; i++) {
                wmma::fragment<wmma::matrix_a, 16, 16, 16, bf16, wmma::row_major> fah, fal;
                int r = warpRow * 32 + i * 16;
                wmma::load_matrix_sync(fah, cAh + r * PA + kk, PA);
                wmma::load_matrix_sync(fal, cAl + r * PA + kk, PA);
#pragma unroll
                for (int j = 0; j < 4; j++) {
                    wmma::mma_sync(acc[i][j], fah, fbh[j], acc[i][j]);
                    wmma::mma_sync(acc[i][j], fah, fbl[j], acc[i][j]);
                    wmma::mma_sync(acc[i][j], fal, fbh[j], acc[i][j]);
                }
            }
        }
        __syncthreads();
    }

    // ---- epilogue ----
    float* st = sStage + wid * 16 * 20;
#pragma unroll
    for (int i = 0; i < 2; i++) {
#pragma unroll
        for (int j = 0; j < 4; j++) {
            wmma::store_matrix_sync(st, acc[i][j], 20, wmma::mem_row_major);
            __syncwarp();
            int gr0 = brow + warpRow * 32 + i * 16;
            int gc0 = bcol + warpCol * 64 + j * 16;
#pragma unroll
            for (int e = 0; e < 8; e++) {
                int idx = e * 32 + lane;
                int r = idx >> 4, c = idx & 15;
                int gr = gr0 + r;
                if (gr < M) {
                    size_t off = (size_t)gr * N + gc0 + c;
                    float v = st[r * 20 + c] + bias[gc0 + c];
                    if (epi == 1) {
                        Cf[off] = v + R[off];
                    } else if (epi == 2) {
                        v = 0.5f * v * (1.0f + erff(v * 0.70710678118654752f));
                        bf16 hh, ll; splitv(v, hh, ll);
                        Ch[off] = hh; Cl[off] = ll;
                    } else {
                        Cf[off] = v;
                    }
                }
            }
            __syncwarp();
        }
    }
}

// ---------------- LayerNorm: fp32 out + bf16 hi/lo out ----------------
__global__ void layernorm_kernel(const float* __restrict__ x, const float* __restrict__ g,
                                 const float* __restrict__ b, float* __restrict__ out,
                                 bf16* __restrict__ oh, bf16* __restrict__ ol)
{
    __shared__ float xs[D_];
    __shared__ float red[8];
    __shared__ float s_mean, s_rstd;

    int row = blockIdx.x;
    const float* xr = x + (size_t)row * D_;
    int tid  = threadIdx.x;
    int lane = tid & 31, warp = tid >> 5;

    float s = 0.f;
    for (int i = tid; i < D_; i += 256) { float v = xr[i]; xs[i] = v; s += v; }
#pragma unroll
    for (int o = 16; o; o >>= 1) s += __shfl_xor_sync(0xffffffffu, s, o);
    if (lane == 0) red[warp] = s;
    __syncthreads();
    if (tid == 0) {
        float t = 0.f;
#pragma unroll
        for (int w = 0; w < 8; w++) t += red[w];
        s_mean = t * (1.0f / D_);
    }
    __syncthreads();
    float m = s_mean;

    float v2 = 0.f;
    for (int i = tid; i < D_; i += 256) { float dv = xs[i] - m; v2 += dv * dv; }
#pragma unroll
    for (int o = 16; o; o >>= 1) v2 += __shfl_xor_sync(0xffffffffu, v2, o);
    if (lane == 0) red[warp] = v2;
    __syncthreads();
    if (tid == 0) {
        float t = 0.f;
#pragma unroll
        for (int w = 0; w < 8; w++) t += red[w];
        s_rstd = rsqrtf(t * (1.0f / D_) + 1e-5f);
    }
    __syncthreads();
    float rstd = s_rstd;

    size_t base = (size_t)row * D_;
    for (int i = tid; i < D_; i += 256) {
        float v = (xs[i] - m) * rstd * g[i] + b[i];
        out[base + i] = v;
        bf16 hh, ll; splitv(v, hh, ll);
        oh[base + i] = hh; ol[base + i] = ll;
    }
}

// ---------------- attention: scores = scale * Q Kt (reads fused qkv) -------------
__global__ __launch_bounds__(256)
void qk_kernel(const float* __restrict__ QKV, float* __restrict__ Sc)
{
    const int PITCH = 68;
    __shared__ __align__(16) float Qs[64 * PITCH];
    __shared__ __align__(16) float Ks[64 * PITCH];

    int bh = blockIdx.z;
    int b = bh / H_, h = bh % H_;
    int s0 = blockIdx.y * 64, t0 = blockIdx.x * 64;
    const float* Qb = QKV + (size_t)b * S_ * QS_ + h * DH_;
    const float* Kb = QKV + (size_t)b * S_ * QS_ + 768 + h * DH_;
    int tid = threadIdx.x;

#pragma unroll
    for (int k = 0; k < 16; k++) {
        int idx = tid + k * 256;
        int r = idx >> 6, d = idx & 63;
        float qv = 0.f, kv = 0.f;
        if (s0 + r < S_) qv = Qb[(size_t)(s0 + r) * QS_ + d];
        if (t0 + r < S_) kv = Kb[(size_t)(t0 + r) * QS_ + d];
        Qs[d * PITCH + r] = qv;
        Ks[d * PITCH + r] = kv;
    }
    __syncthreads();

    int tx = tid & 15, ty = tid >> 4;
    float acc[4][4];
#pragma unroll
    for (int i = 0; i < 4; i++)
#pragma unroll
        for (int j = 0; j < 4; j++) acc[i][j] = 0.f;

#pragma unroll 4
    for (int d = 0; d < 64; d++) {
        float4 a = *reinterpret_cast<const float4*>(&Qs[d * PITCH + ty * 4]);
        float4 bb = *reinterpret_cast<const float4*>(&Ks[d * PITCH + tx * 4]);
        float ar[4] = {a.x, a.y, a.z, a.w};
        float br[4] = {bb.x, bb.y, bb.z, bb.w};
#pragma unroll
        for (int i = 0; i < 4; i++)
#pragma unroll
            for (int j = 0; j < 4; j++) acc[i][j] += ar[i] * br[j];
    }

    float* Sb = Sc + (size_t)bh * S_ * S_;
#pragma unroll
    for (int i = 0; i < 4; i++) {
        int s = s0 + ty * 4 + i;
        if (s >= S_) continue;
#pragma unroll
        for (int j = 0; j < 4; j++) {
            int t = t0 + tx * 4 + j;
            if (t >= S_) continue;
            Sb[(size_t)s * S_ + t] = acc[i][j] * 0.125f;
        }
    }
}

// ---------------- softmax ----------------
__global__ void softmax_kernel(float* __restrict__ p, int nrows)
{
    int row = blockIdx.x * 8 + (threadIdx.x >> 5);
    if (row >= nrows) return;
    int lane = threadIdx.x & 31;
    float* pr = p + (size_t)row * S_;

    float m = -1e30f;
    for (int t = lane; t < S_; t += 32) m = fmaxf(m, pr[t]);
#pragma unroll
    for (int o = 16; o; o >>= 1) m = fmaxf(m, __shfl_xor_sync(0xffffffffu, m, o));

    float s = 0.f;
    for (int t = lane; t < S_; t += 32) { float e = expf(pr[t] - m); pr[t] = e; s += e; }
#pragma unroll
    for (int o = 16; o; o >>= 1) s += __shfl_xor_sync(0xffffffffu, s, o);

    float inv = 1.0f / s;
    for (int t = lane; t < S_; t += 32) pr[t] *= inv;
}

// ---------------- attention: O = P @ V (writes bf16 hi/lo) ----------------
__global__ __launch_bounds__(256)
void pv_kernel(const float* __restrict__ P, const float* __restrict__ QKV,
               bf16* __restrict__ Oh, bf16* __restrict__ Ol)
{
    const int PITCH = 68;
    __shared__ __align__(16) float Ps[32 * PITCH];
    __shared__ __align__(16) float Vs[32 * PITCH];

    int bh = blockIdx.y;
    int b = bh / H_, h = bh % H_;
    int s0 = blockIdx.x * 64;
    const float* Pb = P + (size_t)bh * S_ * S_;
    const float* Vb = QKV + (size_t)b * S_ * QS_ + 1536 + h * DH_;
    int tid = threadIdx.x;
    int tx = tid & 15, ty = tid >> 4;

    float acc[4][4];
#pragma unroll
    for (int i = 0; i < 4; i++)
#pragma unroll
        for (int j = 0; j < 4; j++) acc[i][j] = 0.f;

    for (int t0 = 0; t0 < S_; t0 += 32) {
#pragma unroll
        for (int k = 0; k < 8; k++) {
            int idx = tid + k * 256;
            int r = idx >> 5, t = idx & 31;
            float pv = 0.f;
            if (s0 + r < S_ && t0 + t < S_) pv = Pb[(size_t)(s0 + r) * S_ + t0 + t];
            Ps[t * PITCH + r] = pv;
        }
#pragma unroll
        for (int k = 0; k < 8; k++) {
            int idx = tid + k * 256;
            int t = idx >> 6, d = idx & 63;
            float vv = 0.f;
            if (t0 + t < S_) vv = Vb[(size_t)(t0 + t) * QS_ + d];
            Vs[t * PITCH + d] = vv;
        }
        __syncthreads();

#pragma unroll 4
        for (int t = 0; t < 32; t++) {
            float4 a = *reinterpret_cast<const float4*>(&Ps[t * PITCH + ty * 4]);
            float4 bb = *reinterpret_cast<const float4*>(&Vs[t * PITCH + tx * 4]);
            float ar[4] = {a.x, a.y, a.z, a.w};
            float br[4] = {bb.x, bb.y, bb.z, bb.w};
#pragma unroll
            for (int i = 0; i < 4; i++)
#pragma unroll
                for (int j = 0; j < 4; j++) acc[i][j] += ar[i] * br[j];
        }
        __syncthreads();
    }

#pragma unroll
    for (int i = 0; i < 4; i++) {
        int s = s0 + ty * 4 + i;
        if (s >= S_) continue;
#pragma unroll
        for (int j = 0; j < 4; j++) {
            int d = tx * 4 + j;
            size_t off = ((size_t)(b * S_ + s)) * D_ + h * DH_ + d;
            bf16 hh, ll; splitv(acc[i][j], hh, ll);
            Oh[off] = hh; Ol[off] = ll;
        }
    }
}

// ---------------- classification head ----------------
__global__ void head_kernel(const float* __restrict__ Xn, const float* __restrict__ W,
                            const float* __restrict__ bias, float* __restrict__ out)
{
    __shared__ float xs[D_];
    int b = blockIdx.y;
    const float* xr = Xn + (size_t)b * S_ * D_;
    for (int i = threadIdx.x; i < D_; i += 256) xs[i] = xr[i];
    __syncthreads();

    int n = blockIdx.x * 256 + threadIdx.x;
    if (n >= NCLS_) return;
    float s = bias[n];
    for (int k = 0; k < D_; k++) s += xs[k] * W[(size_t)k * NCLS_ + n];
    out[b * NCLS_ + n] = s;
}

// ---------------- host launch ----------------
static inline void run_gemm(const bf16* Ah, const bf16* Al, const bf16* Bh, const bf16* Bl,
                            const float* bias, const float* R,
                            float* Cf, bf16* Ch, bf16* Cl, int M, int N, int K, int epi)
{
    dim3 grid(N / 256, (M + 127) / 128);
    gemm_dual_kernel<<<grid, 512, GEMM_SMEM>>>(Ah, Al, Bh, Bl, bias, R, Cf, Ch, Cl, M, N, K, epi);
}

extern "C" void kernel_launch(void* const* d_in, const int* in_sizes, int n_in,
                              void* d_out, int out_size)
{
    const float* X       = (const float*)d_in[0];
    const float* patch_w = (const float*)d_in[1];
    const float* patch_b = (const float*)d_in[2];
    const float* cls_tok = (const float*)d_in[3];
    const float* pos_emb = (const float*)d_in[4];
    const float* ln1_g   = (const float*)d_in[5];
    const float* ln1_b   = (const float*)d_in[6];
    const float* Wq      = (const float*)d_in[7];
    const float* bq      = (const float*)d_in[8];
    const float* Wk      = (const float*)d_in[9];
    const float* bk      = (const float*)d_in[10];
    const float* Wv      = (const float*)d_in[11];
    const float* bv      = (const float*)d_in[12];
    const float* Wo      = (const float*)d_in[13];
    const float* bo      = (const float*)d_in[14];
    const float* ln2_g   = (const float*)d_in[15];
    const float* ln2_b   = (const float*)d_in[16];
    const float* Wf1     = (const float*)d_in[17];
    const float* bf1     = (const float*)d_in[18];
    const float* Wf2     = (const float*)d_in[19];
    const float* bf2     = (const float*)d_in[20];
    const float* lnf_g   = (const float*)d_in[21];
    const float* lnf_b   = (const float*)d_in[22];
    const float* head_w  = (const float*)d_in[23];
    const float* head_b  = (const float*)d_in[24];
    float* out = (float*)d_out;
    (void)in_sizes; (void)n_in; (void)out_size;

    cudaFuncSetAttribute(gemm_dual_kernel, cudaFuncAttributeMaxDynamicSharedMemorySize, GEMM_SMEM);

    float *px, *plnf, *pqkv, *ppe, *psc, *pbqkv;
    bf16 *plnh, *plnl, *pattnh, *pattnl, *pffhh, *pffhl, *pimh, *piml;
    bf16 *pwpth, *pwptl, *pwqkvh, *pwqkvl, *pwoh, *pwol, *pwf1h, *pwf1l, *pwf2h, *pwf2l;
    cudaGetSymbolAddress((void**)&px,    g_x);
    cudaGetSymbolAddress((void**)&plnf,  g_lnb);
    cudaGetSymbolAddress((void**)&plnh,  g_lnh);
    cudaGetSymbolAddress((void**)&plnl,  g_lnl);
    cudaGetSymbolAddress((void**)&pqkv,  g_qkv);
    cudaGetSymbolAddress((void**)&pattnh,g_attnh);
    cudaGetSymbolAddress((void**)&pattnl,g_attnl);
    cudaGetSymbolAddress((void**)&pffhh, g_ffhh);
    cudaGetSymbolAddress((void**)&pffhl, g_ffhl);
    cudaGetSymbolAddress((void**)&psc,   g_sc);
    cudaGetSymbolAddress((void**)&pimh,  g_imh);
    cudaGetSymbolAddress((void**)&piml,  g_iml);
    cudaGetSymbolAddress((void**)&ppe,   g_pe);
    cudaGetSymbolAddress((void**)&pwpth, g_wpt_h);
    cudaGetSymbolAddress((void**)&pwptl, g_wpt_l);
    cudaGetSymbolAddress((void**)&pwqkvh,g_wqkv_h);
    cudaGetSymbolAddress((void**)&pwqkvl,g_wqkv_l);
    cudaGetSymbolAddress((void**)&pbqkv, g_bqkv);
    cudaGetSymbolAddress((void**)&pwoh,  g_wo_h);
    cudaGetSymbolAddress((void**)&pwol,  g_wo_l);
    cudaGetSymbolAddress((void**)&pwf1h, g_wf1_h);
    cudaGetSymbolAddress((void**)&pwf1l, g_wf1_l);
    cudaGetSymbolAddress((void**)&pwf2h, g_wf2_h);
    cudaGetSymbolAddress((void**)&pwf2l, g_wf2_l);

    // --- prep: split weights ---
    {
        size_t nqkv = (size_t)L_ * D_ * QS_;
        qkv_split_kernel<<<(unsigned)((nqkv + 255) / 256), 256>>>(Wq, Wk, Wv, pwqkvh, pwqkvl);
        qkv_bias_kernel<<<(L_ * QS_ + 255) / 256, 256>>>(bq, bk, bv, pbqkv);
        size_t nwo = (size_t)L_ * D_ * D_;
        split_kernel<<<(unsigned)((nwo + 255) / 256), 256>>>(Wo, pwoh, pwol, nwo);
        size_t nf = (size_t)L_ * D_ * F_;
        split_kernel<<<(unsigned)((nf + 255) / 256), 256>>>(Wf1, pwf1h, pwf1l, nf);
        split_kernel<<<(unsigned)((nf + 255) / 256), 256>>>(Wf2, pwf2h, pwf2l, nf);
        transpose_split_kernel<<<(D_ * D_ + 255) / 256, 256>>>(patch_w, pwpth, pwptl);
    }

    // --- patch embedding ---
    {
        int n1 = B_ * NPATCH * D_;
        im2col_kernel<<<(n1 + 255) / 256, 256>>>(X, pimh, piml);
        run_gemm(pimh, piml, pwpth, pwptl, patch_b, nullptr,
                 ppe, nullptr, nullptr, B_ * NPATCH, D_, D_, 0);
        int n2 = BS_ * D_;
        assemble_kernel<<<(n2 + 255) / 256, 256>>>(ppe, cls_tok, pos_emb, px);
    }

    const int nrows_sm = B_ * H_ * S_;

    for (int l = 0; l < L_; l++) {
        layernorm_kernel<<<BS_, 256>>>(px, ln1_g + l * D_, ln1_b + l * D_, plnf, plnh, plnl);

        // fused QKV GEMM: [BS,768] @ [768,2304]
        run_gemm(plnh, plnl, pwqkvh + (size_t)l * D_ * QS_, pwqkvl + (size_t)l * D_ * QS_,
                 pbqkv + l * QS_, nullptr, pqkv, nullptr, nullptr, BS_, QS_, D_, 0);

        {
            dim3 grid((S_ + 63) / 64, (S_ + 63) / 64, B_ * H_);
            qk_kernel<<<grid, 256>>>(pqkv, psc);
        }
        softmax_kernel<<<(nrows_sm + 7) / 8, 256>>>(psc, nrows_sm);
        {
            dim3 grid((S_ + 63) / 64, B_ * H_);
            pv_kernel<<<grid, 256>>>(psc, pqkv, pattnh, pattnl);
        }

        // out proj + residual
        run_gemm(pattnh, pattnl, pwoh + (size_t)l * D_ * D_, pwol + (size_t)l * D_ * D_,
                 bo + l * D_, px, px, nullptr, nullptr, BS_, D_, D_, 1);

        layernorm_kernel<<<BS_, 256>>>(px, ln2_g + l * D_, ln2_b + l * D_, plnf, plnh, plnl);

        // FFN1 (GELU, bf16 hi/lo out)
        run_gemm(plnh, plnl, pwf1h + (size_t)l * D_ * F_, pwf1l + (size_t)l * D_ * F_,
                 bf1 + l * F_, nullptr, nullptr, pffhh, pffhl, BS_, F_, D_, 2);
        // FFN2 + residual
        run_gemm(pffhh, pffhl, pwf2h + (size_t)l * F_ * D_, pwf2l + (size_t)l * F_ * D_,
                 bf2 + l * D_, px, px, nullptr, nullptr, BS_, D_, F_, 1);
    }

    layernorm_kernel<<<BS_, 256>>>(px, lnf_g, lnf_b, plnf, plnh, plnl);
    {
        dim3 grid((NCLS_ + 255) / 256, B_);
        head_kernel<<<grid, 256>>>(plnf, head_w, head_b, out);
    }
}